// round 8
// baseline (speedup 1.0000x reference)
#include <cuda_runtime.h>
#include <math.h>

#define T_LEN 160
#define B_SZ  640
#define IN_F  40
#define H_SZ  256
#define G_SZ  1024
#define N_SPK 64
#define M_UTT 10
#define KC    32
#define KPAD  36       // smem row pitch (floats) for bulk tiles; 144B = 16B-aligned

#define NBT   8        // batch tiles
#define BT    80       // batch rows per block (8*80 = 640)
#define NCT   16       // col tiles (hn tiles)
#define HN_T  16       // hn per block
#define HS_PAD 260     // padded row stride for h tile (256+4; 1040B, 16B-aligned)

// ---------------- device scratch (static globals; no runtime alloc) ----------
static __device__ float g_Xg[(size_t)T_LEN * B_SZ * G_SZ];     // precomputed input gates
static __device__ float g_hseq[(size_t)T_LEN * B_SZ * H_SZ];   // h sequence (recurrence exchange buffer)
static __device__ float g_c[B_SZ * H_SZ];                      // final cell state
static __device__ float g_E1[B_SZ * H_SZ];
static __device__ float g_En[B_SZ * H_SZ];
static __device__ float g_C[N_SPK * H_SZ];
static __device__ float g_Cn[N_SPK * H_SZ];
static __device__ float g_d[B_SZ];
static __device__ unsigned int g_bar[NBT];                     // per-btile step barrier

// ---------------- f32x2 helpers ---------------------------------------------
// fma.rn.f32x2: d = a*b + d elementwise on packed fp32 pairs (SASS FFMA2).
__device__ __forceinline__ void fma2(unsigned long long& d,
                                     unsigned long long a,
                                     unsigned long long b) {
    asm("fma.rn.f32x2 %0, %1, %2, %0;" : "+l"(d) : "l"(a), "l"(b));
}
__device__ __forceinline__ float f2sum(unsigned long long v) {
    float2 p;
    asm("mov.b64 {%0, %1}, %2;" : "=f"(p.x), "=f"(p.y) : "l"(v));
    return p.x + p.y;
}

// ---------------- misc helpers ----------------------------------------------
__device__ __forceinline__ float block_sum(float v, float* sh) {
    int tid = threadIdx.x;
    #pragma unroll
    for (int o = 16; o > 0; o >>= 1) v += __shfl_down_sync(0xffffffffu, v, o);
    if ((tid & 31) == 0) sh[tid >> 5] = v;
    __syncthreads();
    int nw = blockDim.x >> 5;
    float r = (tid < nw) ? sh[tid] : 0.f;
    if (tid < 32) {
        #pragma unroll
        for (int o = 16; o > 0; o >>= 1) r += __shfl_down_sync(0xffffffffu, r, o);
        if (tid == 0) sh[0] = r;
    }
    __syncthreads();
    float out = sh[0];
    __syncthreads();
    return out;
}

__device__ __forceinline__ float sigf(float x) { return 1.f / (1.f + __expf(-x)); }

// ---------------- barrier reset ---------------------------------------------
__global__ void init_bar_kernel() {
    if (threadIdx.x < NBT) g_bar[threadIdx.x] = 0u;
}

// ---------------- bulk input GEMM: Xg = A @ Wih^T + (bih + bhh) -------------
// FFMA2 microkernel: accumulators are f32x2 pairs over adjacent k.
__global__ void bulk_gemm_kernel(const float* __restrict__ A,
                                 const float* __restrict__ W,
                                 const float* __restrict__ bih,
                                 const float* __restrict__ bhh,
                                 int K, int mode)
{
    __shared__ __align__(16) float As[64][KPAD];
    __shared__ __align__(16) float Bs[64][KPAD];

    const int row0 = blockIdx.y * 64;
    const int col0 = blockIdx.x * 64;
    const int tid  = threadIdx.x;          // 128
    const int tx   = tid & 7;
    const int ty   = tid >> 3;

    unsigned long long acc2[4][8];
    #pragma unroll
    for (int r = 0; r < 4; r++)
        #pragma unroll
        for (int c = 0; c < 8; c++) acc2[r][c] = 0ull;

    const float* src = (mode == 0) ? A : g_hseq;
    const int nk = (K + KC - 1) / KC;

    for (int kc = 0; kc < nk; kc++) {
        const int kbase = kc * KC;
        for (int idx = tid; idx < 64 * KC; idx += 128) {
            int r = idx >> 5, kk = idx & 31;
            int k = kbase + kk;
            float v = 0.f;
            if (k < K) {
                int row = row0 + r;
                if (mode == 0) {
                    int t = row / B_SZ;
                    int b = row - t * B_SZ;
                    v = src[(size_t)b * (T_LEN * IN_F) + (size_t)t * IN_F + k];
                } else {
                    v = src[(size_t)row * K + k];
                }
            }
            As[r][kk] = v;
        }
        for (int idx = tid; idx < 64 * KC; idx += 128) {
            int r = idx >> 5, kk = idx & 31;
            int k = kbase + kk;
            Bs[r][kk] = (k < K) ? W[(size_t)(col0 + r) * K + k] : 0.f;
        }
        __syncthreads();

        #pragma unroll
        for (int kp = 0; kp < KC / 4; kp++) {       // k-quads
            const int k0 = kp * 4;
            ulonglong2 a2[4];
            #pragma unroll
            for (int r = 0; r < 4; r++)
                a2[r] = *reinterpret_cast<const ulonglong2*>(&As[ty * 4 + r][k0]);
            ulonglong2 w2[8];
            #pragma unroll
            for (int c = 0; c < 8; c++)
                w2[c] = *reinterpret_cast<const ulonglong2*>(&Bs[tx + c * 8][k0]);
            #pragma unroll
            for (int r = 0; r < 4; r++)
                #pragma unroll
                for (int c = 0; c < 8; c++) {
                    fma2(acc2[r][c], a2[r].x, w2[c].x);
                    fma2(acc2[r][c], a2[r].y, w2[c].y);
                }
        }
        __syncthreads();
    }

    #pragma unroll
    for (int r = 0; r < 4; r++) {
        int row = row0 + ty * 4 + r;
        #pragma unroll
        for (int c = 0; c < 8; c++) {
            int col = col0 + tx + c * 8;
            g_Xg[(size_t)row * G_SZ + col] = f2sum(acc2[r][c]) + bih[col] + bhh[col];
        }
    }
}

// ---------------- persistent LSTM recurrence (one launch per layer) ----------
// Grid (NCT, NBT) = (16, 8) = 128 blocks, 256 threads, 1 block/SM.
// Whh slice resident in SMEM, re-laid-out so k-pairs are adjacent per (nx,g):
//   ws[ ((k>>1)*16 + nx)*8 + g*2 + (k&1) ]
// so each (k-pair, gate) is one 64-bit f32x2 operand. c/h carried in registers.
__global__ void __launch_bounds__(256)
lstm_persistent_kernel(const float* __restrict__ Whh,
                       const int* __restrict__ lens)
{
    extern __shared__ __align__(16) float sm[];
    float* ws = sm;                 // 16384 floats (64 KB)
    float* hs = sm + 16384;         // [b=80][HS_PAD=260]

    const int tid = threadIdx.x;    // 256
    const int nx  = tid & 15;       // hn lane
    const int by  = tid >> 4;       // 0..15, batch rows by*5..+4
    const int n0  = blockIdx.x * HN_T;
    const int b0  = blockIdx.y * BT;
    const int hn  = n0 + nx;
    const unsigned bt = blockIdx.y;

    // ---- load W slice into smem, k-pair interleaved layout ----
    for (int i = 0; i < 64; i++) {
        int lin = tid + i * 256;           // 0..16383
        int k   = lin & 255;
        int col = lin >> 8;                // 0..63
        int wnx = col >> 2;
        int wg  = col & 3;
        ws[(((k >> 1) * 16 + wnx) << 3) + wg * 2 + (k & 1)] =
            Whh[(size_t)(wg * H_SZ + n0 + wnx) * H_SZ + k];
    }

    // ---- per-thread state ----
    int   len_r[5];
    float c_r[5], h_r[5];
    #pragma unroll
    for (int r = 0; r < 5; r++) {
        len_r[r] = lens[b0 + by * 5 + r];
        c_r[r] = 0.f;
        h_r[r] = 0.f;
    }

    __syncthreads();   // ws ready

    for (int t = 0; t < T_LEN; t++) {
        // ---- prefetch Xg gate values (independent of h) ----
        float xg[5][4];
        #pragma unroll
        for (int r = 0; r < 5; r++) {
            const float* xrow = g_Xg + ((size_t)t * B_SZ + b0 + by * 5 + r) * G_SZ;
            #pragma unroll
            for (int g = 0; g < 4; g++) xg[r][g] = xrow[g * H_SZ + hn];
        }

        float acc[5][4];

        if (t > 0) {
            // ---- load h_{t-1} tile [80,256] into smem (float4) ----
            const float* hp = g_hseq + (size_t)(t - 1) * B_SZ * H_SZ;
            #pragma unroll
            for (int i = 0; i < 20; i++) {
                int lin = tid + i * 256;       // 0..5119 float4 slots
                int b   = lin >> 6;            // 0..79
                int kq  = lin & 63;            // float4 index within row
                float4 v = *(const float4*)(hp + (size_t)(b0 + b) * H_SZ + kq * 4);
                *(float4*)&hs[b * HS_PAD + kq * 4] = v;
            }
            __syncthreads();

            // ---- FFMA2 GEMM: acc2 packs adjacent k in f32x2 lanes ----
            unsigned long long acc2[5][4];
            #pragma unroll
            for (int r = 0; r < 5; r++)
                #pragma unroll
                for (int g = 0; g < 4; g++) acc2[r][g] = 0ull;

            #pragma unroll 4
            for (int kq = 0; kq < 64; kq++) {
                const int k0 = kq * 4;
                // a: one 16B load per row = pairs (k0,k0+1) and (k0+2,k0+3)
                ulonglong2 a2[5];
                #pragma unroll
                for (int r = 0; r < 5; r++)
                    a2[r] = *reinterpret_cast<const ulonglong2*>(
                                &hs[(by * 5 + r) * HS_PAD + k0]);
                // w: pair p0 = 2kq (gates 0..3), pair p1 = 2kq+1
                const ulonglong2* wp0 = reinterpret_cast<const ulonglong2*>(
                                            &ws[((2 * kq) * 16 + nx) << 3]);
                const ulonglong2* wp1 = reinterpret_cast<const ulonglong2*>(
                                            &ws[((2 * kq + 1) * 16 + nx) << 3]);
                ulonglong2 w0a = wp0[0], w0b = wp0[1];   // p0: {g0,g1},{g2,g3}
                ulonglong2 w1a = wp1[0], w1b = wp1[1];   // p1
                #pragma unroll
                for (int r = 0; r < 5; r++) {
                    fma2(acc2[r][0], a2[r].x, w0a.x);
                    fma2(acc2[r][1], a2[r].x, w0a.y);
                    fma2(acc2[r][2], a2[r].x, w0b.x);
                    fma2(acc2[r][3], a2[r].x, w0b.y);
                    fma2(acc2[r][0], a2[r].y, w1a.x);
                    fma2(acc2[r][1], a2[r].y, w1a.y);
                    fma2(acc2[r][2], a2[r].y, w1b.x);
                    fma2(acc2[r][3], a2[r].y, w1b.y);
                }
            }
            #pragma unroll
            for (int r = 0; r < 5; r++)
                #pragma unroll
                for (int g = 0; g < 4; g++) acc[r][g] = f2sum(acc2[r][g]);
        } else {
            #pragma unroll
            for (int r = 0; r < 5; r++)
                #pragma unroll
                for (int g = 0; g < 4; g++) acc[r][g] = 0.f;
        }

        // ---- LSTM cell + mask, write h ----
        float* hout_base = g_hseq + (size_t)t * B_SZ * H_SZ;
        #pragma unroll
        for (int r = 0; r < 5; r++) {
            const int b = b0 + by * 5 + r;
            const bool valid = (t < len_r[r]);
            float gi = acc[r][0] + xg[r][0];
            float gf = acc[r][1] + xg[r][1];
            float gg = acc[r][2] + xg[r][2];
            float go = acc[r][3] + xg[r][3];
            float cn = sigf(gf) * c_r[r] + sigf(gi) * tanhf(gg);
            float hv = sigf(go) * tanhf(cn);
            float ho = valid ? hv : h_r[r];
            float co = valid ? cn : c_r[r];
            c_r[r] = co;
            h_r[r] = ho;
            hout_base[(size_t)b * H_SZ + hn] = ho;
        }

        // ---- per-btile barrier (16 col-blocks) ----
        if (t < T_LEN - 1) {
            __threadfence();
            __syncthreads();
            if (tid == 0) {
                atomicAdd(&g_bar[bt], 1u);
                const unsigned target = (unsigned)(NCT * (t + 1));
                while (*(volatile unsigned int*)&g_bar[bt] < target) __nanosleep(64);
                __threadfence();
            }
            __syncthreads();
        }
    }

    // ---- write final cell state ----
    #pragma unroll
    for (int r = 0; r < 5; r++)
        g_c[(size_t)(b0 + by * 5 + r) * H_SZ + hn] = c_r[r];
}

// ---------------- scoring ---------------------------------------------------
__global__ void score_norm_kernel() {
    __shared__ float sh[32];
    int b = blockIdx.x, tid = threadIdx.x;
    float e = g_c[b * H_SZ + tid];
    float n1 = sqrtf(block_sum(e * e, sh));
    float e1 = e / fmaxf(n1, 1e-12f);
    float n2 = sqrtf(block_sum(e1 * e1, sh));
    float en = e1 / fmaxf(n2, 1e-8f);
    g_E1[b * H_SZ + tid] = e1;
    g_En[b * H_SZ + tid] = en;
}

__global__ void score_centroid_kernel() {
    __shared__ float sh[32];
    int i = blockIdx.x, tid = threadIdx.x;
    float s = 0.f;
    #pragma unroll
    for (int j = 0; j < M_UTT; j++) s += g_E1[(i * M_UTT + j) * H_SZ + tid];
    float c = s * (1.f / M_UTT);
    float n = sqrtf(block_sum(c * c, sh));
    g_C[i * H_SZ + tid]  = c;
    g_Cn[i * H_SZ + tid] = c / fmaxf(n, 1e-8f);
}

__global__ void score_diag_kernel() {
    __shared__ float sh[32];
    int b = blockIdx.x, tid = threadIdx.x;
    float cm = ((float)M_UTT * g_C[(b / M_UTT) * H_SZ + tid] + g_E1[b * H_SZ + tid])
               * (1.f / (M_UTT - 1));
    float n = sqrtf(block_sum(cm * cm, sh));
    float cmn = cm / fmaxf(n, 1e-8f);
    float d = block_sum(g_En[b * H_SZ + tid] * cmn, sh);
    if (tid == 0) g_d[b] = d;
}

__global__ void score_sim_kernel(const float* __restrict__ wsim,
                                 const float* __restrict__ bsim,
                                 float* __restrict__ out)
{
    __shared__ float en[H_SZ];
    int b = blockIdx.x;
    for (int k = threadIdx.x; k < H_SZ; k += 64) en[k] = g_En[b * H_SZ + k];
    __syncthreads();
    int i = threadIdx.x;  // 0..63
    float dot = 0.f;
    #pragma unroll 8
    for (int k = 0; k < H_SZ; k++) dot += en[k] * g_Cn[i * H_SZ + k];
    float w = *wsim, bs = *bsim;
    float val = (i == b / M_UTT) ? g_d[b] : dot;
    out[b * N_SPK + i] = val * w + bs;
}

// ---------------- launch ----------------------------------------------------
extern "C" void kernel_launch(void* const* d_in, const int* in_sizes, int n_in,
                              void* d_out, int out_size)
{
    (void)n_in; (void)out_size;
    const float* seq  = (const float*)d_in[0];
    const int*   lens = (const int*)d_in[1];

    // Input ordering: setup_inputs() dict insertion order:
    //   0: sequences, 1: len_sequences, 2: w_sim, 3: b_sim, 4..: per-layer W/b
    const float *Wih[3], *Whh[3], *bih[3], *bhh[3], *wsim, *bsim;
    if (in_sizes[2] == 1) {
        wsim = (const float*)d_in[2];
        bsim = (const float*)d_in[3];
        for (int l = 0; l < 3; l++) {
            Wih[l] = (const float*)d_in[4 + 4 * l];
            Whh[l] = (const float*)d_in[5 + 4 * l];
            bih[l] = (const float*)d_in[6 + 4 * l];
            bhh[l] = (const float*)d_in[7 + 4 * l];
        }
    } else {
        for (int l = 0; l < 3; l++) {
            Wih[l] = (const float*)d_in[2 + 4 * l];
            Whh[l] = (const float*)d_in[3 + 4 * l];
            bih[l] = (const float*)d_in[4 + 4 * l];
            bhh[l] = (const float*)d_in[5 + 4 * l];
        }
        wsim = (const float*)d_in[14];
        bsim = (const float*)d_in[15];
    }
    float* out = (float*)d_out;

    const int smem_bytes = (16384 + BT * HS_PAD) * sizeof(float);  // ~148.7 KB
    cudaFuncSetAttribute(lstm_persistent_kernel,
                         cudaFuncAttributeMaxDynamicSharedMemorySize, smem_bytes);

    const dim3 bulk_grid(G_SZ / 64, (T_LEN * B_SZ) / 64);   // (16, 1600)
    const dim3 pers_grid(NCT, NBT);                          // (16, 8) = 128 blocks

    for (int l = 0; l < 3; l++) {
        int K    = (l == 0) ? IN_F : H_SZ;
        int mode = (l == 0) ? 0 : 1;
        bulk_gemm_kernel<<<bulk_grid, 128>>>(seq, Wih[l], bih[l], bhh[l], K, mode);
        init_bar_kernel<<<1, 32>>>();
        lstm_persistent_kernel<<<pers_grid, 256, smem_bytes>>>(Whh[l], lens);
    }

    score_norm_kernel<<<B_SZ, H_SZ>>>();
    score_centroid_kernel<<<N_SPK, H_SZ>>>();
    score_diag_kernel<<<B_SZ, H_SZ>>>();
    score_sim_kernel<<<B_SZ, 64>>>(wsim, bsim, out);
}

// round 9
// speedup vs baseline: 1.0160x; 1.0160x over previous
#include <cuda_runtime.h>
#include <math.h>

#define T_LEN 160
#define B_SZ  640
#define IN_F  40
#define H_SZ  256
#define G_SZ  1024
#define N_SPK 64
#define M_UTT 10
#define KC    32
#define KPAD  36       // bulk smem row pitch (floats); 144B, 16B-aligned

#define NBT   8        // batch tiles
#define BT    80       // batch rows per block
#define NCT   16       // col tiles (hn tiles)
#define WPITCH 260     // persistent ws k-pitch (floats); 1040B = 65*16 ✓
#define WS_FLOATS (64 * WPITCH)          // 64 cols (16 hn x 4 g) x 260
#define HS_PAD 260     // h tile row pitch

// ---------------- device scratch --------------------------------------------
static __device__ float g_Xg[(size_t)T_LEN * B_SZ * G_SZ];
static __device__ float g_hseq[(size_t)T_LEN * B_SZ * H_SZ];
static __device__ float g_c[B_SZ * H_SZ];
static __device__ float g_E1[B_SZ * H_SZ];
static __device__ float g_En[B_SZ * H_SZ];
static __device__ float g_C[N_SPK * H_SZ];
static __device__ float g_Cn[N_SPK * H_SZ];
static __device__ float g_d[B_SZ];
static __device__ unsigned int g_bar[NBT];

// ---------------- f32x2 helpers ---------------------------------------------
__device__ __forceinline__ void fma2(unsigned long long& d,
                                     unsigned long long a,
                                     unsigned long long b) {
    asm("fma.rn.f32x2 %0, %1, %2, %0;" : "+l"(d) : "l"(a), "l"(b));
}
__device__ __forceinline__ float f2sum(unsigned long long v) {
    float2 p;
    asm("mov.b64 {%0, %1}, %2;" : "=f"(p.x), "=f"(p.y) : "l"(v));
    return p.x + p.y;
}

// ---------------- misc helpers ----------------------------------------------
__device__ __forceinline__ float block_sum(float v, float* sh) {
    int tid = threadIdx.x;
    #pragma unroll
    for (int o = 16; o > 0; o >>= 1) v += __shfl_down_sync(0xffffffffu, v, o);
    if ((tid & 31) == 0) sh[tid >> 5] = v;
    __syncthreads();
    int nw = blockDim.x >> 5;
    float r = (tid < nw) ? sh[tid] : 0.f;
    if (tid < 32) {
        #pragma unroll
        for (int o = 16; o > 0; o >>= 1) r += __shfl_down_sync(0xffffffffu, r, o);
        if (tid == 0) sh[0] = r;
    }
    __syncthreads();
    float out = sh[0];
    __syncthreads();
    return out;
}

__device__ __forceinline__ float sigf(float x) { return 1.f / (1.f + __expf(-x)); }

__global__ void init_bar_kernel() {
    if (threadIdx.x < NBT) g_bar[threadIdx.x] = 0u;
}

// ---------------- bulk input GEMM: Xg = A @ Wih^T + (bih + bhh) -------------
// 64x64 tile, 256 threads. warp = 8 rows (a-loads broadcast across lanes),
// lane = 2 adjacent cols (k-contiguous FFMA2 operands). acc2[8][2] = 32 regs.
__global__ void __launch_bounds__(256)
bulk_gemm_kernel(const float* __restrict__ A,
                 const float* __restrict__ W,
                 const float* __restrict__ bih,
                 const float* __restrict__ bhh,
                 int K, int mode)
{
    __shared__ __align__(16) float As[64][KPAD];
    __shared__ __align__(16) float Bs[64][KPAD];

    const int row0 = blockIdx.y * 64;
    const int col0 = blockIdx.x * 64;
    const int tid  = threadIdx.x;          // 256
    const int warp = tid >> 5;             // 0..7 -> rows warp*8..+7
    const int lane = tid & 31;
    const int c0   = 2 * lane;             // local cols c0, c0+1

    unsigned long long acc2[8][2];
    #pragma unroll
    for (int r = 0; r < 8; r++) { acc2[r][0] = 0ull; acc2[r][1] = 0ull; }

    const float* src = (mode == 0) ? A : g_hseq;
    const int nk = (K + KC - 1) / KC;

    for (int kc = 0; kc < nk; kc++) {
        const int kbase = kc * KC;
        for (int idx = tid; idx < 64 * KC; idx += 256) {
            int r = idx >> 5, kk = idx & 31;
            int k = kbase + kk;
            float v = 0.f;
            if (k < K) {
                int row = row0 + r;
                if (mode == 0) {
                    int t = row / B_SZ;
                    int b = row - t * B_SZ;
                    v = src[(size_t)b * (T_LEN * IN_F) + (size_t)t * IN_F + k];
                } else {
                    v = src[(size_t)row * K + k];
                }
            }
            As[r][kk] = v;
        }
        for (int idx = tid; idx < 64 * KC; idx += 256) {
            int r = idx >> 5, kk = idx & 31;
            int k = kbase + kk;
            Bs[r][kk] = (k < K) ? W[(size_t)(col0 + r) * K + k] : 0.f;
        }
        __syncthreads();

        #pragma unroll
        for (int kq = 0; kq < KC / 4; kq++) {
            const int k0 = kq * 4;
            ulonglong2 w0 = *reinterpret_cast<const ulonglong2*>(&Bs[c0][k0]);
            ulonglong2 w1 = *reinterpret_cast<const ulonglong2*>(&Bs[c0 + 1][k0]);
            #pragma unroll
            for (int r = 0; r < 8; r++) {
                ulonglong2 a2 = *reinterpret_cast<const ulonglong2*>(
                                    &As[warp * 8 + r][k0]);   // broadcast
                fma2(acc2[r][0], a2.x, w0.x);
                fma2(acc2[r][0], a2.y, w0.y);
                fma2(acc2[r][1], a2.x, w1.x);
                fma2(acc2[r][1], a2.y, w1.y);
            }
        }
        __syncthreads();
    }

    const int col = col0 + c0;
    const float bias0 = bih[col] + bhh[col];
    const float bias1 = bih[col + 1] + bhh[col + 1];
    #pragma unroll
    for (int r = 0; r < 8; r++) {
        int row = row0 + warp * 8 + r;
        float2 o;
        o.x = f2sum(acc2[r][0]) + bias0;
        o.y = f2sum(acc2[r][1]) + bias1;
        *reinterpret_cast<float2*>(&g_Xg[(size_t)row * G_SZ + col]) = o;
    }
}

// ---------------- persistent LSTM recurrence --------------------------------
// Grid (16, 8) = 128 blocks, 256 threads, 1 block/SM.
// warp = 10 batch rows; lane = (hnx 0..15, rowHalf 0..1) -> 5 rows x 1 hn x 4 g.
// ws[c][k]: c = g*16+hnx, k-contiguous (pitch 260) -> 16B FFMA2 operands.
// a-loads broadcast (2 distinct addrs/warp). Gates thread-local -> reg epilogue.
__global__ void __launch_bounds__(256)
lstm_persistent_kernel(const float* __restrict__ Whh,
                       const int* __restrict__ lens)
{
    extern __shared__ __align__(16) float sm[];
    float* ws = sm;                       // [64][WPITCH]
    float* hs = sm + WS_FLOATS;           // [80][HS_PAD]

    const int tid  = threadIdx.x;         // 256
    const int warp = tid >> 5;            // 0..7
    const int lane = tid & 31;
    const int hnx  = lane & 15;
    const int rh   = lane >> 4;
    const int rbase = warp * 10 + rh * 5; // 5 local rows rbase..rbase+4
    const int n0 = blockIdx.x * 16;
    const int b0 = blockIdx.y * BT;
    const int hn = n0 + hnx;
    const unsigned bt = blockIdx.y;

    // ---- W slice -> smem: ws[(g*16+hx)*WPITCH + k] ----
    for (int lin = tid; lin < 64 * 256; lin += 256) {
        int k = lin & 255;
        int c = lin >> 8;                 // 0..63
        int g  = c >> 4;
        int hx = c & 15;
        ws[c * WPITCH + k] = Whh[(size_t)(g * H_SZ + n0 + hx) * H_SZ + k];
    }

    int   len_r[5];
    float c_r[5], h_r[5];
    #pragma unroll
    for (int r = 0; r < 5; r++) {
        len_r[r] = lens[b0 + rbase + r];
        c_r[r] = 0.f;
        h_r[r] = 0.f;
    }

    __syncthreads();

    for (int t = 0; t < T_LEN; t++) {
        // ---- Xg prefetch (global, independent of h) ----
        float xg[5][4];
        #pragma unroll
        for (int r = 0; r < 5; r++) {
            const float* xrow = g_Xg + ((size_t)t * B_SZ + b0 + rbase + r) * G_SZ;
            #pragma unroll
            for (int g = 0; g < 4; g++) xg[r][g] = xrow[g * H_SZ + hn];
        }

        float acc[5][4];

        if (t > 0) {
            const float* hp = g_hseq + (size_t)(t - 1) * B_SZ * H_SZ;
            #pragma unroll
            for (int i = 0; i < 20; i++) {
                int lin = tid + i * 256;
                int b   = lin >> 6;
                int kq  = lin & 63;
                float4 v = *(const float4*)(hp + (size_t)(b0 + b) * H_SZ + kq * 4);
                *(float4*)&hs[b * HS_PAD + kq * 4] = v;
            }
            __syncthreads();

            unsigned long long acc2[5][4];
            #pragma unroll
            for (int r = 0; r < 5; r++)
                #pragma unroll
                for (int g = 0; g < 4; g++) acc2[r][g] = 0ull;

            #pragma unroll 4
            for (int kq = 0; kq < 64; kq++) {
                const int k0 = kq * 4;
                ulonglong2 w0 = *reinterpret_cast<const ulonglong2*>(
                                    &ws[(0 * 16 + hnx) * WPITCH + k0]);
                ulonglong2 w1 = *reinterpret_cast<const ulonglong2*>(
                                    &ws[(1 * 16 + hnx) * WPITCH + k0]);
                ulonglong2 w2 = *reinterpret_cast<const ulonglong2*>(
                                    &ws[(2 * 16 + hnx) * WPITCH + k0]);
                ulonglong2 w3 = *reinterpret_cast<const ulonglong2*>(
                                    &ws[(3 * 16 + hnx) * WPITCH + k0]);
                #pragma unroll
                for (int r = 0; r < 5; r++) {
                    ulonglong2 a2 = *reinterpret_cast<const ulonglong2*>(
                                        &hs[(rbase + r) * HS_PAD + k0]);  // broadcast
                    fma2(acc2[r][0], a2.x, w0.x);
                    fma2(acc2[r][0], a2.y, w0.y);
                    fma2(acc2[r][1], a2.x, w1.x);
                    fma2(acc2[r][1], a2.y, w1.y);
                    fma2(acc2[r][2], a2.x, w2.x);
                    fma2(acc2[r][2], a2.y, w2.y);
                    fma2(acc2[r][3], a2.x, w3.x);
                    fma2(acc2[r][3], a2.y, w3.y);
                }
            }
            #pragma unroll
            for (int r = 0; r < 5; r++)
                #pragma unroll
                for (int g = 0; g < 4; g++) acc[r][g] = f2sum(acc2[r][g]);
        } else {
            #pragma unroll
            for (int r = 0; r < 5; r++)
                #pragma unroll
                for (int g = 0; g < 4; g++) acc[r][g] = 0.f;
        }

        // ---- LSTM cell + mask, write h ----
        float* hout_base = g_hseq + (size_t)t * B_SZ * H_SZ;
        #pragma unroll
        for (int r = 0; r < 5; r++) {
            const int b = b0 + rbase + r;
            const bool valid = (t < len_r[r]);
            float gi = acc[r][0] + xg[r][0];
            float gf = acc[r][1] + xg[r][1];
            float gg = acc[r][2] + xg[r][2];
            float go = acc[r][3] + xg[r][3];
            float cn = sigf(gf) * c_r[r] + sigf(gi) * tanhf(gg);
            float hv = sigf(go) * tanhf(cn);
            float ho = valid ? hv : h_r[r];
            float co = valid ? cn : c_r[r];
            c_r[r] = co;
            h_r[r] = ho;
            hout_base[(size_t)b * H_SZ + hn] = ho;
        }

        // ---- per-btile barrier (16 col-blocks) ----
        if (t < T_LEN - 1) {
            __threadfence();
            __syncthreads();
            if (tid == 0) {
                atomicAdd(&g_bar[bt], 1u);
                const unsigned target = (unsigned)(NCT * (t + 1));
                while (*(volatile unsigned int*)&g_bar[bt] < target) __nanosleep(64);
                __threadfence();
            }
            __syncthreads();
        }
    }

    #pragma unroll
    for (int r = 0; r < 5; r++)
        g_c[(size_t)(b0 + rbase + r) * H_SZ + hn] = c_r[r];
}

// ---------------- scoring ---------------------------------------------------
__global__ void score_norm_kernel() {
    __shared__ float sh[32];
    int b = blockIdx.x, tid = threadIdx.x;
    float e = g_c[b * H_SZ + tid];
    float n1 = sqrtf(block_sum(e * e, sh));
    float e1 = e / fmaxf(n1, 1e-12f);
    float n2 = sqrtf(block_sum(e1 * e1, sh));
    float en = e1 / fmaxf(n2, 1e-8f);
    g_E1[b * H_SZ + tid] = e1;
    g_En[b * H_SZ + tid] = en;
}

__global__ void score_centroid_kernel() {
    __shared__ float sh[32];
    int i = blockIdx.x, tid = threadIdx.x;
    float s = 0.f;
    #pragma unroll
    for (int j = 0; j < M_UTT; j++) s += g_E1[(i * M_UTT + j) * H_SZ + tid];
    float c = s * (1.f / M_UTT);
    float n = sqrtf(block_sum(c * c, sh));
    g_C[i * H_SZ + tid]  = c;
    g_Cn[i * H_SZ + tid] = c / fmaxf(n, 1e-8f);
}

__global__ void score_diag_kernel() {
    __shared__ float sh[32];
    int b = blockIdx.x, tid = threadIdx.x;
    float cm = ((float)M_UTT * g_C[(b / M_UTT) * H_SZ + tid] + g_E1[b * H_SZ + tid])
               * (1.f / (M_UTT - 1));
    float n = sqrtf(block_sum(cm * cm, sh));
    float cmn = cm / fmaxf(n, 1e-8f);
    float d = block_sum(g_En[b * H_SZ + tid] * cmn, sh);
    if (tid == 0) g_d[b] = d;
}

__global__ void score_sim_kernel(const float* __restrict__ wsim,
                                 const float* __restrict__ bsim,
                                 float* __restrict__ out)
{
    __shared__ float en[H_SZ];
    int b = blockIdx.x;
    for (int k = threadIdx.x; k < H_SZ; k += 64) en[k] = g_En[b * H_SZ + k];
    __syncthreads();
    int i = threadIdx.x;  // 0..63
    float dot = 0.f;
    #pragma unroll 8
    for (int k = 0; k < H_SZ; k++) dot += en[k] * g_Cn[i * H_SZ + k];
    float w = *wsim, bs = *bsim;
    float val = (i == b / M_UTT) ? g_d[b] : dot;
    out[b * N_SPK + i] = val * w + bs;
}

// ---------------- launch ----------------------------------------------------
extern "C" void kernel_launch(void* const* d_in, const int* in_sizes, int n_in,
                              void* d_out, int out_size)
{
    (void)n_in; (void)out_size;
    const float* seq  = (const float*)d_in[0];
    const int*   lens = (const int*)d_in[1];

    const float *Wih[3], *Whh[3], *bih[3], *bhh[3], *wsim, *bsim;
    if (in_sizes[2] == 1) {               // dict order (expected)
        wsim = (const float*)d_in[2];
        bsim = (const float*)d_in[3];
        for (int l = 0; l < 3; l++) {
            Wih[l] = (const float*)d_in[4 + 4 * l];
            Whh[l] = (const float*)d_in[5 + 4 * l];
            bih[l] = (const float*)d_in[6 + 4 * l];
            bhh[l] = (const float*)d_in[7 + 4 * l];
        }
    } else {
        for (int l = 0; l < 3; l++) {
            Wih[l] = (const float*)d_in[2 + 4 * l];
            Whh[l] = (const float*)d_in[3 + 4 * l];
            bih[l] = (const float*)d_in[4 + 4 * l];
            bhh[l] = (const float*)d_in[5 + 4 * l];
        }
        wsim = (const float*)d_in[14];
        bsim = (const float*)d_in[15];
    }
    float* out = (float*)d_out;

    const int smem_bytes = (WS_FLOATS + BT * HS_PAD) * sizeof(float);  // ~146 KB
    cudaFuncSetAttribute(lstm_persistent_kernel,
                         cudaFuncAttributeMaxDynamicSharedMemorySize, smem_bytes);

    const dim3 bulk_grid(G_SZ / 64, (T_LEN * B_SZ) / 64);   // (16, 1600)
    const dim3 pers_grid(NCT, NBT);                          // (16, 8)

    for (int l = 0; l < 3; l++) {
        int K    = (l == 0) ? IN_F : H_SZ;
        int mode = (l == 0) ? 0 : 1;
        bulk_gemm_kernel<<<bulk_grid, 256>>>(seq, Wih[l], bih[l], bhh[l], K, mode);
        init_bar_kernel<<<1, 32>>>();
        lstm_persistent_kernel<<<pers_grid, 256, smem_bytes>>>(Whh[l], lens);
    }

    score_norm_kernel<<<B_SZ, H_SZ>>>();
    score_centroid_kernel<<<N_SPK, H_SZ>>>();
    score_diag_kernel<<<B_SZ, H_SZ>>>();
    score_sim_kernel<<<B_SZ, 64>>>(wsim, bsim, out);
}

// round 10
// speedup vs baseline: 1.3645x; 1.3431x over previous
#include <cuda_runtime.h>
#include <math.h>
#include <stdint.h>

#define T_LEN 160
#define B_SZ  640
#define IN_F  40
#define H_SZ  256
#define G_SZ  1024
#define N_SPK 64
#define M_UTT 10

#define NBT   8        // batch tiles (recurrence)
#define BT    80       // batch rows per block
#define NCT   16       // col tiles
#define HN_T  16
#define HS_PAD 260

#define APITCH 36      // smem pitch for tf32 tiles (144B, 16B-aligned, conflict-free frags)

// ---------------- device scratch --------------------------------------------
static __device__ float g_Xg[(size_t)T_LEN * B_SZ * G_SZ];     // 419 MB
static __device__ float g_hseq[(size_t)T_LEN * B_SZ * H_SZ];   // 105 MB
static __device__ float g_Ah[(size_t)T_LEN * B_SZ * H_SZ];     // 105 MB  A-hi (tf32)
static __device__ float g_Al[(size_t)T_LEN * B_SZ * H_SZ];     // 105 MB  A-lo (tf32)
static __device__ float g_Wh[G_SZ * H_SZ];                     // 1 MB    W-hi
static __device__ float g_Wl[G_SZ * H_SZ];                     // 1 MB    W-lo
static __device__ float g_c[B_SZ * H_SZ];
static __device__ float g_E1[B_SZ * H_SZ];
static __device__ float g_En[B_SZ * H_SZ];
static __device__ float g_C[N_SPK * H_SZ];
static __device__ float g_Cn[N_SPK * H_SZ];
static __device__ float g_d[B_SZ];
static __device__ unsigned int g_bar[NBT];

// ---------------- helpers ---------------------------------------------------
__device__ __forceinline__ float tf32_rna(float v) {
    uint32_t r;
    asm("cvt.rna.tf32.f32 %0, %1;" : "=r"(r) : "f"(v));
    return __uint_as_float(r);
}

__device__ __forceinline__ void mma_tf32(float* d, const uint32_t* a,
                                         uint32_t b0, uint32_t b1) {
    asm volatile(
        "mma.sync.aligned.m16n8k8.row.col.f32.tf32.tf32.f32 "
        "{%0,%1,%2,%3}, {%4,%5,%6,%7}, {%8,%9}, {%0,%1,%2,%3};"
        : "+f"(d[0]), "+f"(d[1]), "+f"(d[2]), "+f"(d[3])
        : "r"(a[0]), "r"(a[1]), "r"(a[2]), "r"(a[3]), "r"(b0), "r"(b1));
}

__device__ __forceinline__ float block_sum(float v, float* sh) {
    int tid = threadIdx.x;
    #pragma unroll
    for (int o = 16; o > 0; o >>= 1) v += __shfl_down_sync(0xffffffffu, v, o);
    if ((tid & 31) == 0) sh[tid >> 5] = v;
    __syncthreads();
    int nw = blockDim.x >> 5;
    float r = (tid < nw) ? sh[tid] : 0.f;
    if (tid < 32) {
        #pragma unroll
        for (int o = 16; o > 0; o >>= 1) r += __shfl_down_sync(0xffffffffu, r, o);
        if (tid == 0) sh[0] = r;
    }
    __syncthreads();
    float out = sh[0];
    __syncthreads();
    return out;
}

__device__ __forceinline__ float sigf(float x) { return 1.f / (1.f + __expf(-x)); }

__global__ void init_bar_kernel() {
    if (threadIdx.x < NBT) g_bar[threadIdx.x] = 0u;
}

// ---------------- hi/lo splitters (3xTF32 decomposition) --------------------
// W[1024, K] -> g_Wh/g_Wl laid out [1024, P] (P = padded K), zero-padded.
__global__ void split_w_kernel(const float* __restrict__ W, int K, int P) {
    int idx = blockIdx.x * 256 + threadIdx.x;
    if (idx >= G_SZ * P) return;
    int row = idx / P, k = idx - row * P;
    float v = (k < K) ? W[row * K + k] : 0.f;
    float hi = tf32_rna(v);
    float lo = tf32_rna(v - hi);
    g_Wh[idx] = hi;
    g_Wl[idx] = lo;
}

// A (mode0: sequences [B,T,IN]; mode1: g_hseq [T*B, H]) -> g_Ah/g_Al [T*B, P].
__global__ void split_a_kernel(const float* __restrict__ seq, int K, int P, int mode) {
    size_t idx = (size_t)blockIdx.x * 256 + threadIdx.x;
    if (idx >= (size_t)T_LEN * B_SZ * P) return;
    int row = (int)(idx / P), k = (int)(idx - (size_t)row * P);
    float v = 0.f;
    if (k < K) {
        if (mode == 0) {
            int t = row / B_SZ, b = row - t * B_SZ;
            v = seq[(size_t)b * (T_LEN * IN_F) + (size_t)t * IN_F + k];
        } else {
            v = g_hseq[(size_t)row * H_SZ + k];
        }
    }
    float hi = tf32_rna(v);
    float lo = tf32_rna(v - hi);
    g_Ah[idx] = hi;
    g_Al[idx] = lo;
}

// ---------------- bulk GEMM on tensor pipe: Xg = A @ W^T + bias -------------
// 3xTF32: acc += Ah*Wh + Al*Wh + Ah*Wl.  Tile 128(M) x 64(N), 256 thr, 8 warps.
// Warp w: rows [w*16, w*16+16), all 64 cols (8 n-subtiles of m16n8k8).
__global__ void __launch_bounds__(256)
bulk_tf32_kernel(const float* __restrict__ bih,
                 const float* __restrict__ bhh,
                 int P)
{
    extern __shared__ __align__(16) float ts[];
    float* Ah = ts;                        // [128][APITCH]
    float* Al = Ah + 128 * APITCH;
    float* Bh = Al + 128 * APITCH;         // [64][APITCH]
    float* Bl = Bh + 64 * APITCH;

    const int tid  = threadIdx.x;
    const int warp = tid >> 5;
    const int lane = tid & 31;
    const int gid  = lane >> 2;            // 0..7
    const int tig  = lane & 3;             // 0..3
    const int row0 = blockIdx.y * 128;
    const int col0 = blockIdx.x * 64;
    const int m0   = warp * 16;

    float acc[8][4];
    #pragma unroll
    for (int s = 0; s < 8; s++)
        #pragma unroll
        for (int j = 0; j < 4; j++) acc[s][j] = 0.f;

    for (int kc = 0; kc < P; kc += 32) {
        // A tiles: 128 rows x 8 float4 = 1024 slots
        #pragma unroll
        for (int i = 0; i < 4; i++) {
            int slot = tid + i * 256;
            int r = slot >> 3, q = slot & 7;
            size_t src = (size_t)(row0 + r) * P + kc + q * 4;
            *(float4*)&Ah[r * APITCH + q * 4] = *(const float4*)&g_Ah[src];
            *(float4*)&Al[r * APITCH + q * 4] = *(const float4*)&g_Al[src];
        }
        // B tiles: 64 rows x 8 float4 = 512 slots
        #pragma unroll
        for (int i = 0; i < 2; i++) {
            int slot = tid + i * 256;
            int r = slot >> 3, q = slot & 7;
            size_t src = (size_t)(col0 + r) * P + kc + q * 4;
            *(float4*)&Bh[r * APITCH + q * 4] = *(const float4*)&g_Wh[src];
            *(float4*)&Bl[r * APITCH + q * 4] = *(const float4*)&g_Wl[src];
        }
        __syncthreads();

        #pragma unroll
        for (int ks = 0; ks < 4; ks++) {
            const int k0 = ks * 8;
            uint32_t ah[4], al[4];
            ah[0] = __float_as_uint(Ah[(m0 + gid)     * APITCH + k0 + tig]);
            ah[1] = __float_as_uint(Ah[(m0 + gid + 8) * APITCH + k0 + tig]);
            ah[2] = __float_as_uint(Ah[(m0 + gid)     * APITCH + k0 + tig + 4]);
            ah[3] = __float_as_uint(Ah[(m0 + gid + 8) * APITCH + k0 + tig + 4]);
            al[0] = __float_as_uint(Al[(m0 + gid)     * APITCH + k0 + tig]);
            al[1] = __float_as_uint(Al[(m0 + gid + 8) * APITCH + k0 + tig]);
            al[2] = __float_as_uint(Al[(m0 + gid)     * APITCH + k0 + tig + 4]);
            al[3] = __float_as_uint(Al[(m0 + gid + 8) * APITCH + k0 + tig + 4]);
            #pragma unroll
            for (int sub = 0; sub < 8; sub++) {
                uint32_t bh0 = __float_as_uint(Bh[(sub * 8 + gid) * APITCH + k0 + tig]);
                uint32_t bh1 = __float_as_uint(Bh[(sub * 8 + gid) * APITCH + k0 + tig + 4]);
                uint32_t bl0 = __float_as_uint(Bl[(sub * 8 + gid) * APITCH + k0 + tig]);
                uint32_t bl1 = __float_as_uint(Bl[(sub * 8 + gid) * APITCH + k0 + tig + 4]);
                mma_tf32(acc[sub], ah, bh0, bh1);
                mma_tf32(acc[sub], al, bh0, bh1);
                mma_tf32(acc[sub], ah, bl0, bl1);
            }
        }
        __syncthreads();
    }

    // epilogue: d0/d1 -> row m0+gid, cols 2tig,2tig+1; d2/d3 -> row m0+gid+8
    #pragma unroll
    for (int sub = 0; sub < 8; sub++) {
        const int col = col0 + sub * 8 + 2 * tig;
        const float bias0 = bih[col] + bhh[col];
        const float bias1 = bih[col + 1] + bhh[col + 1];
        const int r1 = row0 + m0 + gid;
        float2 o1 = {acc[sub][0] + bias0, acc[sub][1] + bias1};
        *(float2*)&g_Xg[(size_t)r1 * G_SZ + col] = o1;
        float2 o2 = {acc[sub][2] + bias0, acc[sub][3] + bias1};
        *(float2*)&g_Xg[(size_t)(r1 + 8) * G_SZ + col] = o2;
    }
}

// ---------------- persistent LSTM recurrence (R6 scalar version) ------------
__global__ void __launch_bounds__(256)
lstm_persistent_kernel(const float* __restrict__ Whh,
                       const int* __restrict__ lens)
{
    extern __shared__ float sm[];
    float* ws = sm;                 // [k=256][nx=16][g=4]
    float* hs = sm + 16384;         // [b=80][HS_PAD]

    const int tid = threadIdx.x;
    const int nx  = tid & 15;
    const int by  = tid >> 4;
    const int n0  = blockIdx.x * HN_T;
    const int b0  = blockIdx.y * BT;
    const int hn  = n0 + nx;
    const unsigned bt = blockIdx.y;

    for (int i = 0; i < 64; i++) {
        int lin = tid + i * 256;
        int k   = lin & 255;
        int col = lin >> 8;
        int wnx = col >> 2;
        int wg  = col & 3;
        ws[(k * 16 + wnx) * 4 + wg] = Whh[(size_t)(wg * H_SZ + n0 + wnx) * H_SZ + k];
    }

    int   len_r[5];
    float c_r[5], h_r[5];
    #pragma unroll
    for (int r = 0; r < 5; r++) {
        len_r[r] = lens[b0 + by * 5 + r];
        c_r[r] = 0.f;
        h_r[r] = 0.f;
    }

    __syncthreads();

    for (int t = 0; t < T_LEN; t++) {
        float xg[5][4];
        #pragma unroll
        for (int r = 0; r < 5; r++) {
            const float* xrow = g_Xg + ((size_t)t * B_SZ + b0 + by * 5 + r) * G_SZ;
            #pragma unroll
            for (int g = 0; g < 4; g++) xg[r][g] = xrow[g * H_SZ + hn];
        }

        float acc[5][4];
        #pragma unroll
        for (int r = 0; r < 5; r++)
            #pragma unroll
            for (int g = 0; g < 4; g++) acc[r][g] = 0.f;

        if (t > 0) {
            const float* hp = g_hseq + (size_t)(t - 1) * B_SZ * H_SZ;
            #pragma unroll
            for (int i = 0; i < 20; i++) {
                int lin = tid + i * 256;
                int b   = lin >> 6;
                int kq  = lin & 63;
                float4 v = *(const float4*)(hp + (size_t)(b0 + b) * H_SZ + kq * 4);
                *(float4*)&hs[b * HS_PAD + kq * 4] = v;
            }
            __syncthreads();

            #pragma unroll 4
            for (int kq = 0; kq < 64; kq++) {
                const int k0 = kq * 4;
                float4 a[5];
                #pragma unroll
                for (int r = 0; r < 5; r++)
                    a[r] = *(const float4*)&hs[(by * 5 + r) * HS_PAD + k0];
                #pragma unroll
                for (int j = 0; j < 4; j++) {
                    float4 w = *(const float4*)&ws[((k0 + j) * 16 + nx) * 4];
                    #pragma unroll
                    for (int r = 0; r < 5; r++) {
                        float av = (j == 0) ? a[r].x : (j == 1) ? a[r].y
                                 : (j == 2) ? a[r].z : a[r].w;
                        acc[r][0] += av * w.x;
                        acc[r][1] += av * w.y;
                        acc[r][2] += av * w.z;
                        acc[r][3] += av * w.w;
                    }
                }
            }
        }

        float* hout_base = g_hseq + (size_t)t * B_SZ * H_SZ;
        #pragma unroll
        for (int r = 0; r < 5; r++) {
            const int b = b0 + by * 5 + r;
            const bool valid = (t < len_r[r]);
            float gi = acc[r][0] + xg[r][0];
            float gf = acc[r][1] + xg[r][1];
            float gg = acc[r][2] + xg[r][2];
            float go = acc[r][3] + xg[r][3];
            float cn = sigf(gf) * c_r[r] + sigf(gi) * tanhf(gg);
            float hv = sigf(go) * tanhf(cn);
            float ho = valid ? hv : h_r[r];
            float co = valid ? cn : c_r[r];
            c_r[r] = co;
            h_r[r] = ho;
            hout_base[(size_t)b * H_SZ + hn] = ho;
        }

        if (t < T_LEN - 1) {
            __threadfence();
            __syncthreads();
            if (tid == 0) {
                atomicAdd(&g_bar[bt], 1u);
                const unsigned target = (unsigned)(NCT * (t + 1));
                while (*(volatile unsigned int*)&g_bar[bt] < target) __nanosleep(64);
                __threadfence();
            }
            __syncthreads();
        }
    }

    #pragma unroll
    for (int r = 0; r < 5; r++)
        g_c[(size_t)(b0 + by * 5 + r) * H_SZ + hn] = c_r[r];
}

// ---------------- scoring ---------------------------------------------------
__global__ void score_norm_kernel() {
    __shared__ float sh[32];
    int b = blockIdx.x, tid = threadIdx.x;
    float e = g_c[b * H_SZ + tid];
    float n1 = sqrtf(block_sum(e * e, sh));
    float e1 = e / fmaxf(n1, 1e-12f);
    float n2 = sqrtf(block_sum(e1 * e1, sh));
    float en = e1 / fmaxf(n2, 1e-8f);
    g_E1[b * H_SZ + tid] = e1;
    g_En[b * H_SZ + tid] = en;
}

__global__ void score_centroid_kernel() {
    __shared__ float sh[32];
    int i = blockIdx.x, tid = threadIdx.x;
    float s = 0.f;
    #pragma unroll
    for (int j = 0; j < M_UTT; j++) s += g_E1[(i * M_UTT + j) * H_SZ + tid];
    float c = s * (1.f / M_UTT);
    float n = sqrtf(block_sum(c * c, sh));
    g_C[i * H_SZ + tid]  = c;
    g_Cn[i * H_SZ + tid] = c / fmaxf(n, 1e-8f);
}

__global__ void score_diag_kernel() {
    __shared__ float sh[32];
    int b = blockIdx.x, tid = threadIdx.x;
    float cm = ((float)M_UTT * g_C[(b / M_UTT) * H_SZ + tid] + g_E1[b * H_SZ + tid])
               * (1.f / (M_UTT - 1));
    float n = sqrtf(block_sum(cm * cm, sh));
    float cmn = cm / fmaxf(n, 1e-8f);
    float d = block_sum(g_En[b * H_SZ + tid] * cmn, sh);
    if (tid == 0) g_d[b] = d;
}

__global__ void score_sim_kernel(const float* __restrict__ wsim,
                                 const float* __restrict__ bsim,
                                 float* __restrict__ out)
{
    __shared__ float en[H_SZ];
    int b = blockIdx.x;
    for (int k = threadIdx.x; k < H_SZ; k += 64) en[k] = g_En[b * H_SZ + k];
    __syncthreads();
    int i = threadIdx.x;
    float dot = 0.f;
    #pragma unroll 8
    for (int k = 0; k < H_SZ; k++) dot += en[k] * g_Cn[i * H_SZ + k];
    float w = *wsim, bs = *bsim;
    float val = (i == b / M_UTT) ? g_d[b] : dot;
    out[b * N_SPK + i] = val * w + bs;
}

// ---------------- launch ----------------------------------------------------
extern "C" void kernel_launch(void* const* d_in, const int* in_sizes, int n_in,
                              void* d_out, int out_size)
{
    (void)n_in; (void)out_size;
    const float* seq  = (const float*)d_in[0];
    const int*   lens = (const int*)d_in[1];

    const float *Wih[3], *Whh[3], *bih[3], *bhh[3], *wsim, *bsim;
    if (in_sizes[2] == 1) {               // dict order (expected)
        wsim = (const float*)d_in[2];
        bsim = (const float*)d_in[3];
        for (int l = 0; l < 3; l++) {
            Wih[l] = (const float*)d_in[4 + 4 * l];
            Whh[l] = (const float*)d_in[5 + 4 * l];
            bih[l] = (const float*)d_in[6 + 4 * l];
            bhh[l] = (const float*)d_in[7 + 4 * l];
        }
    } else {
        for (int l = 0; l < 3; l++) {
            Wih[l] = (const float*)d_in[2 + 4 * l];
            Whh[l] = (const float*)d_in[3 + 4 * l];
            bih[l] = (const float*)d_in[4 + 4 * l];
            bhh[l] = (const float*)d_in[5 + 4 * l];
        }
        wsim = (const float*)d_in[14];
        bsim = (const float*)d_in[15];
    }
    float* out = (float*)d_out;

    const int pers_smem = (16384 + BT * HS_PAD) * sizeof(float);     // ~148.7 KB
    const int bulk_smem = (2 * 128 + 2 * 64) * APITCH * sizeof(float); // 55.3 KB
    cudaFuncSetAttribute(lstm_persistent_kernel,
                         cudaFuncAttributeMaxDynamicSharedMemorySize, pers_smem);
    cudaFuncSetAttribute(bulk_tf32_kernel,
                         cudaFuncAttributeMaxDynamicSharedMemorySize, bulk_smem);

    const dim3 bulk_grid(G_SZ / 64, (T_LEN * B_SZ) / 128);   // (16, 800)
    const dim3 pers_grid(NCT, NBT);                           // (16, 8)

    for (int l = 0; l < 3; l++) {
        const int K = (l == 0) ? IN_F : H_SZ;
        const int P = (l == 0) ? 64 : H_SZ;      // padded K (mult of 32)
        const int mode = (l == 0) ? 0 : 1;
        split_w_kernel<<<(G_SZ * P + 255) / 256, 256>>>(Wih[l], K, P);
        split_a_kernel<<<(int)(((size_t)T_LEN * B_SZ * P + 255) / 256), 256>>>(seq, K, P, mode);
        bulk_tf32_kernel<<<bulk_grid, 256, bulk_smem>>>(bih[l], bhh[l], P);
        init_bar_kernel<<<1, 32>>>();
        lstm_persistent_kernel<<<pers_grid, 256, pers_smem>>>(Whh[l], lens);
    }

    score_norm_kernel<<<B_SZ, H_SZ>>>();
    score_centroid_kernel<<<N_SPK, H_SZ>>>();
    score_diag_kernel<<<B_SZ, H_SZ>>>();
    score_sim_kernel<<<B_SZ, 64>>>(wsim, bsim, out);
}